// round 8
// baseline (speedup 1.0000x reference)
#include <cuda_runtime.h>
#include <cuda_bf16.h>
#include <math.h>
#include <stdint.h>

#define Bsz  16
#define Cdim 64
#define Lseq 1024
#define Hn   8
#define HC   512
#define NH   128   // B*H batch-heads

// ---------------- scratch (static device memory; no allocations) ----------------
__device__ float g_PW[1536 * 64];          // packed pointwise weights (q|k|v)
__device__ float g_WF[1536 * 15];          // combined 15-tap depthwise weights
__device__ float g_Q[NH * Lseq * Cdim];    // (n, l, c)  transposed for MMA
__device__ float g_K[NH * Lseq * Cdim];    // (n, l, c)
__device__ float g_V[NH * Cdim * Lseq];    // (n, c, l)
__device__ float g_ATT[Bsz * HC * Lseq];   // (b, hc, l)
__device__ float g_Y[Bsz * Cdim * Lseq];   // after LN1
__device__ float g_H[Bsz * 4 * Cdim * Lseq]; // FFN hidden

__device__ __forceinline__ uint32_t bfpack(float lo, float hi) {
    __nv_bfloat162 h = __floats2bfloat162_rn(lo, hi);   // x=lo (low 16), y=hi
    return *reinterpret_cast<uint32_t*>(&h);
}

// D += A(16x16 bf16 row) * B(16x8 bf16 col)
__device__ __forceinline__ void mma_bf16(float* c, const uint32_t* a, uint32_t b0, uint32_t b1) {
    asm volatile(
        "mma.sync.aligned.m16n8k16.row.col.f32.bf16.bf16.f32 "
        "{%0,%1,%2,%3}, {%4,%5,%6,%7}, {%8,%9}, {%0,%1,%2,%3};"
        : "+f"(c[0]), "+f"(c[1]), "+f"(c[2]), "+f"(c[3])
        : "r"(a[0]), "r"(a[1]), "r"(a[2]), "r"(a[3]), "r"(b0), "r"(b1));
}

// ---------------- K0: fold gate softmax into combined conv weights ----------------
__global__ void combine_kernel(
    const float* __restrict__ pw0, const float* __restrict__ gt0,
    const float* __restrict__ d3_0, const float* __restrict__ d15_0,
    const float* __restrict__ pw1, const float* __restrict__ gt1,
    const float* __restrict__ d3_1, const float* __restrict__ d15_1,
    const float* __restrict__ pw2, const float* __restrict__ gt2,
    const float* __restrict__ d3_2, const float* __restrict__ d15_2,
    float* __restrict__ PW, float* __restrict__ WF)
{
    int o = blockIdx.x * 256 + threadIdx.x;
    if (o >= 1536) return;
    int s = o >> 9, lc = o & 511;
    const float *pw, *gt, *d3, *d15;
    if (s == 0)      { pw = pw0; gt = gt0; d3 = d3_0; d15 = d15_0; }
    else if (s == 1) { pw = pw1; gt = gt1; d3 = d3_1; d15 = d15_1; }
    else             { pw = pw2; gt = gt2; d3 = d3_2; d15 = d15_2; }
    float a = gt[0], b = gt[1];
    float mx = fmaxf(a, b);
    float e0 = expf(a - mx), e1 = expf(b - mx);
    float inv = 1.0f / (e0 + e1);
    float ga = e0 * inv, gb = e1 * inv;
    for (int c = 0; c < 64; c++) PW[(size_t)o * 64 + c] = pw[(size_t)lc * 64 + c];
    for (int t = 0; t < 15; t++) {
        float w = gb * d15[lc * 15 + t];
        if (t >= 6 && t < 9) w += ga * d3[lc * 3 + (t - 6)];
        WF[o * 15 + t] = w;
    }
}

// ---------------- K1: fused pointwise GEMM + depthwise conv15 -> Q/K/V ----------------
__global__ __launch_bounds__(256) void qkv_kernel(
    const float* __restrict__ q,
    const float* __restrict__ PW, const float* __restrict__ WF,
    float* __restrict__ Qp, float* __restrict__ Kp, float* __restrict__ Vp)
{
    extern __shared__ float sm1[];
    float* xs  = sm1;               // [64][144]
    float* mid = xs + 64 * 144;     // [32][144]
    float* spw = mid + 32 * 144;    // [32][64]
    float* swf = spw + 32 * 64;     // [32][16]
    int tid = threadIdx.x;
    int l0 = blockIdx.x * 128;
    int o0 = blockIdx.y * 32;
    int b  = blockIdx.z;

    for (int e = tid; e < 64 * 144; e += 256) {
        int c = e / 144, j = e - c * 144;
        int gl = l0 - 7 + j;
        float v = 0.f;
        if (gl >= 0 && gl < Lseq) v = q[((size_t)b * 64 + c) * Lseq + gl];
        xs[c * 144 + j] = v;
    }
    for (int e = tid; e < 32 * 64; e += 256) spw[e] = PW[(size_t)o0 * 64 + e];
    for (int e = tid; e < 32 * 15; e += 256) {
        int o = e / 15, t = e - o * 15;
        swf[o * 16 + t] = WF[(size_t)(o0 + o) * 15 + t];
    }
    __syncthreads();

    for (int e = tid; e < 32 * 36; e += 256) {
        int o = e / 36, jq = e - o * 36;
        const float* pwrow = spw + o * 64;
        const float* xcol  = xs + jq * 4;
        float4 acc = make_float4(0.f, 0.f, 0.f, 0.f);
#pragma unroll 8
        for (int c = 0; c < 64; c++) {
            float w = pwrow[c];
            float4 xv = *(const float4*)(xcol + c * 144);
            acc.x += w * xv.x; acc.y += w * xv.y; acc.z += w * xv.z; acc.w += w * xv.w;
        }
        *(float4*)(mid + o * 144 + jq * 4) = acc;
    }
    __syncthreads();

    int s = o0 >> 9;
    for (int e = tid; e < 32 * 128; e += 256) {
        int o = e >> 7, i = e & 127;
        const float* mrow = mid + o * 144;
        const float* wrow = swf + o * 16;
        float acc = 0.f;
#pragma unroll
        for (int t = 0; t < 15; t++) acc += wrow[t] * mrow[i + t];
        int og = o0 + o;
        int ch = og & 511;
        int head = ch >> 6, c = ch & 63;
        size_t n = (size_t)b * 8 + head;
        if (s == 2) {
            Vp[(n * 64 + c) * Lseq + l0 + i] = acc;                 // (n, c, l)
        } else {
            float* base = (s == 0) ? Qp : Kp;
            base[(n * Lseq + l0 + i) * 64 + c] = acc;               // (n, l, c)
        }
    }
}

// ---------------- K2: flash attention via mma.sync bf16 m16n8k16 ----------------
// grid (8, 128); 256 threads (8 warps x 16 q-rows). static smem 36864 B.
#define KVSTRIDE 72
__global__ __launch_bounds__(256, 2) void attn_bf16(
    const float* __restrict__ Qt, const float* __restrict__ Kt,
    const float* __restrict__ Vg, float* __restrict__ att)
{
    __shared__ __nv_bfloat16 Ks[64 * KVSTRIDE];
    __shared__ __nv_bfloat16 Vs[64 * KVSTRIDE];
    int tid = threadIdx.x, w = tid >> 5, lane = tid & 31;
    int g = lane >> 2, r = lane & 3;
    int n = blockIdx.y, q0 = blockIdx.x * 128;

    const float* Qb = Qt + (size_t)n * (Lseq * 64) + (size_t)(q0 + w * 16) * 64;
    const float* Kb = Kt + (size_t)n * (Lseq * 64);
    const float* Vb = Vg + (size_t)n * (64 * Lseq);

    // ---- Q A-fragments direct from gmem (once per CTA), scaled by 1/8 ----
    uint32_t qf[16];
#pragma unroll
    for (int kc = 0; kc < 4; kc++) {
        float2 x0 = *(const float2*)(Qb + (size_t)g * 64 + kc * 16 + 2 * r);
        float2 x1 = *(const float2*)(Qb + (size_t)(g + 8) * 64 + kc * 16 + 2 * r);
        float2 x2 = *(const float2*)(Qb + (size_t)g * 64 + kc * 16 + 2 * r + 8);
        float2 x3 = *(const float2*)(Qb + (size_t)(g + 8) * 64 + kc * 16 + 2 * r + 8);
        qf[kc * 4 + 0] = bfpack(x0.x * 0.125f, x0.y * 0.125f);
        qf[kc * 4 + 1] = bfpack(x1.x * 0.125f, x1.y * 0.125f);
        qf[kc * 4 + 2] = bfpack(x2.x * 0.125f, x2.y * 0.125f);
        qf[kc * 4 + 3] = bfpack(x3.x * 0.125f, x3.y * 0.125f);
    }

    float oacc[32];
#pragma unroll
    for (int i = 0; i < 32; i++) oacc[i] = 0.f;
    float m0 = -INFINITY, m1 = -INFINITY, l0 = 0.f, l1 = 0.f;

    for (int kt = 0; kt < 16; kt++) {
        int k0 = kt * 64;
        __syncthreads();
        // ---- stage K (key, c) and V (c, key) as bf16, row stride 72 ----
        for (int e = tid; e < 1024; e += 256) {
            int row = e >> 4, cg = e & 15;
            float4 kv = *(const float4*)(Kb + (size_t)(k0 + row) * 64 + cg * 4);
            uint2 kp = make_uint2(bfpack(kv.x, kv.y), bfpack(kv.z, kv.w));
            *(uint2*)(&Ks[row * KVSTRIDE + cg * 4]) = kp;
            float4 vv = *(const float4*)(Vb + (size_t)row * Lseq + k0 + cg * 4);
            uint2 vp = make_uint2(bfpack(vv.x, vv.y), bfpack(vv.z, vv.w));
            *(uint2*)(&Vs[row * KVSTRIDE + cg * 4]) = vp;
        }
        __syncthreads();

        // ---- S = Q K^T : 8 nb x 4 kc mmas ----
        float sacc[32];
#pragma unroll
        for (int i = 0; i < 32; i++) sacc[i] = 0.f;
#pragma unroll
        for (int kc = 0; kc < 4; kc++) {
#pragma unroll
            for (int nb = 0; nb < 8; nb++) {
                const __nv_bfloat16* kr = &Ks[(nb * 8 + g) * KVSTRIDE + kc * 16 + 2 * r];
                uint32_t b0 = *(const uint32_t*)kr;
                uint32_t b1 = *(const uint32_t*)(kr + 8);
                mma_bf16(sacc + nb * 4, qf + kc * 4, b0, b1);
            }
        }

        // ---- online softmax (quad-local rows g / g+8) ----
        float tm0 = -INFINITY, tm1 = -INFINITY;
#pragma unroll
        for (int nb = 0; nb < 8; nb++) {
            tm0 = fmaxf(tm0, fmaxf(sacc[nb * 4 + 0], sacc[nb * 4 + 1]));
            tm1 = fmaxf(tm1, fmaxf(sacc[nb * 4 + 2], sacc[nb * 4 + 3]));
        }
        tm0 = fmaxf(tm0, __shfl_xor_sync(0xffffffffu, tm0, 1));
        tm0 = fmaxf(tm0, __shfl_xor_sync(0xffffffffu, tm0, 2));
        tm1 = fmaxf(tm1, __shfl_xor_sync(0xffffffffu, tm1, 1));
        tm1 = fmaxf(tm1, __shfl_xor_sync(0xffffffffu, tm1, 2));
        float mn0 = fmaxf(m0, tm0), mn1 = fmaxf(m1, tm1);
        float al0 = __expf(m0 - mn0), al1 = __expf(m1 - mn1);
        m0 = mn0; m1 = mn1;
        float s0 = 0.f, s1 = 0.f;
        uint32_t plo[8], phi[8];   // P fragments, no smem round-trip
#pragma unroll
        for (int nb = 0; nb < 8; nb++) {
            float p0 = __expf(sacc[nb * 4 + 0] - mn0);
            float p1 = __expf(sacc[nb * 4 + 1] - mn0);
            float p2 = __expf(sacc[nb * 4 + 2] - mn1);
            float p3 = __expf(sacc[nb * 4 + 3] - mn1);
            s0 += p0 + p1; s1 += p2 + p3;
            plo[nb] = bfpack(p0, p1);
            phi[nb] = bfpack(p2, p3);
        }
        s0 += __shfl_xor_sync(0xffffffffu, s0, 1);
        s0 += __shfl_xor_sync(0xffffffffu, s0, 2);
        s1 += __shfl_xor_sync(0xffffffffu, s1, 1);
        s1 += __shfl_xor_sync(0xffffffffu, s1, 2);
        l0 = l0 * al0 + s0;
        l1 = l1 * al1 + s1;
#pragma unroll
        for (int nb = 0; nb < 8; nb++) {
            oacc[nb * 4 + 0] *= al0; oacc[nb * 4 + 1] *= al0;
            oacc[nb * 4 + 2] *= al1; oacc[nb * 4 + 3] *= al1;
        }

        // ---- O += P V^T : A = P fragments (registers), B = Vs ----
#pragma unroll
        for (int kc = 0; kc < 4; kc++) {
            uint32_t pa[4] = {plo[2 * kc], phi[2 * kc], plo[2 * kc + 1], phi[2 * kc + 1]};
#pragma unroll
            for (int nb = 0; nb < 8; nb++) {
                const __nv_bfloat16* vr = &Vs[(nb * 8 + g) * KVSTRIDE + kc * 16 + 2 * r];
                uint32_t b0 = *(const uint32_t*)vr;
                uint32_t b1 = *(const uint32_t*)(vr + 8);
                mma_bf16(oacc + nb * 4, pa, b0, b1);
            }
        }
    }

    // ---- epilogue: O / l -> att (b, head*64+c, q) ----
    float inv0 = 1.0f / l0, inv1 = 1.0f / l1;
    int bb = n >> 3, head = n & 7;
    int qg0 = q0 + w * 16 + g, qg1 = qg0 + 8;
    float* ab = att + ((size_t)bb * 512 + head * 64) * Lseq;
#pragma unroll
    for (int nb = 0; nb < 8; nb++) {
        int c = nb * 8 + 2 * r;
        ab[(size_t)c * Lseq + qg0]       = oacc[nb * 4 + 0] * inv0;
        ab[(size_t)(c + 1) * Lseq + qg0] = oacc[nb * 4 + 1] * inv0;
        ab[(size_t)c * Lseq + qg1]       = oacc[nb * 4 + 2] * inv1;
        ab[(size_t)(c + 1) * Lseq + qg1] = oacc[nb * 4 + 3] * inv1;
    }
}

// ---------------- K3/K5: (64 x INC) GEMM + bias + residual + channel LayerNorm ----------------
__global__ __launch_bounds__(256) void gemm_res_ln_kernel(
    const float* __restrict__ X, const float* __restrict__ W,
    const float* __restrict__ bias, const float* __restrict__ res,
    const float* __restrict__ gam, const float* __restrict__ bet,
    float* __restrict__ out, int INC)
{
    __shared__ float sx[64 * 68];
    __shared__ float sw[64 * 68];
    int tid = threadIdx.x;
    int l0 = blockIdx.x * 64;
    int b  = blockIdx.y;
    int ty = tid >> 4, tx = tid & 15;
    float acc[4][4];
#pragma unroll
    for (int i = 0; i < 4; i++)
#pragma unroll
        for (int j = 0; j < 4; j++) acc[i][j] = 0.f;

    for (int cb = 0; cb < INC; cb += 64) {
        __syncthreads();
        for (int e = tid * 4; e < 4096; e += 1024) {
            int ci = e >> 6, l = e & 63;
            *(float4*)(sx + ci * 68 + l) =
                *(const float4*)(X + ((size_t)b * INC + cb + ci) * Lseq + l0 + l);
        }
        for (int e = tid; e < 4096; e += 256) {
            int o = e >> 6, ci = e & 63;
            sw[ci * 68 + o] = W[(size_t)o * INC + cb + ci];
        }
        __syncthreads();
#pragma unroll 4
        for (int ci = 0; ci < 64; ci++) {
            float4 wv = *(const float4*)(sw + ci * 68 + ty * 4);
            float4 xv = *(const float4*)(sx + ci * 68 + tx * 4);
            float wr[4] = {wv.x, wv.y, wv.z, wv.w};
            float xr[4] = {xv.x, xv.y, xv.z, xv.w};
#pragma unroll
            for (int i = 0; i < 4; i++)
#pragma unroll
                for (int j = 0; j < 4; j++) acc[i][j] += wr[i] * xr[j];
        }
    }
    int ob = ty * 4, lx = tx * 4;
    float vals[4][4];
#pragma unroll
    for (int i = 0; i < 4; i++) {
        int o = ob + i;
        float bo = bias[o];
        float4 rv = *(const float4*)(res + ((size_t)b * 64 + o) * Lseq + l0 + lx);
        vals[i][0] = acc[i][0] + bo + rv.x;
        vals[i][1] = acc[i][1] + bo + rv.y;
        vals[i][2] = acc[i][2] + bo + rv.z;
        vals[i][3] = acc[i][3] + bo + rv.w;
    }
    __syncthreads();
    float* red1 = sw;
    float* red2 = sw + 1024;
    float* mu_s = sw + 2048;
    float* iv_s = sw + 2112;
#pragma unroll
    for (int j = 0; j < 4; j++) {
        float s1 = vals[0][j] + vals[1][j] + vals[2][j] + vals[3][j];
        float s2 = vals[0][j] * vals[0][j] + vals[1][j] * vals[1][j] +
                   vals[2][j] * vals[2][j] + vals[3][j] * vals[3][j];
        red1[ty * 64 + lx + j] = s1;
        red2[ty * 64 + lx + j] = s2;
    }
    __syncthreads();
    if (tid < 64) {
        float s1 = 0.f, s2 = 0.f;
#pragma unroll
        for (int r = 0; r < 16; r++) { s1 += red1[r * 64 + tid]; s2 += red2[r * 64 + tid]; }
        float mu = s1 * (1.0f / 64.0f);
        float var = s2 * (1.0f / 64.0f) - mu * mu;
        mu_s[tid] = mu;
        iv_s[tid] = rsqrtf(var + 1e-5f);
    }
    __syncthreads();
#pragma unroll
    for (int i = 0; i < 4; i++) {
        int o = ob + i;
        float gg = gam[o], bb = bet[o];
        float4 ov;
        ov.x = (vals[i][0] - mu_s[lx + 0]) * iv_s[lx + 0] * gg + bb;
        ov.y = (vals[i][1] - mu_s[lx + 1]) * iv_s[lx + 1] * gg + bb;
        ov.z = (vals[i][2] - mu_s[lx + 2]) * iv_s[lx + 2] * gg + bb;
        ov.w = (vals[i][3] - mu_s[lx + 3]) * iv_s[lx + 3] * gg + bb;
        *(float4*)(out + ((size_t)b * 64 + o) * Lseq + l0 + lx) = ov;
    }
}

// ---------------- K4: FFN up-projection (256x64) + bias + ReLU ----------------
__global__ __launch_bounds__(256) void ffn1_kernel(
    const float* __restrict__ X, const float* __restrict__ W,
    const float* __restrict__ bias, float* __restrict__ out)
{
    __shared__ float sx[64 * 68];
    __shared__ float sw[64 * 68];
    int tid = threadIdx.x;
    int l0  = blockIdx.x * 64;
    int ob0 = blockIdx.y * 64;
    int b   = blockIdx.z;
    int ty = tid >> 4, tx = tid & 15;
    float acc[4][4];
#pragma unroll
    for (int i = 0; i < 4; i++)
#pragma unroll
        for (int j = 0; j < 4; j++) acc[i][j] = 0.f;

    for (int e = tid * 4; e < 4096; e += 1024) {
        int ci = e >> 6, l = e & 63;
        *(float4*)(sx + ci * 68 + l) =
            *(const float4*)(X + ((size_t)b * 64 + ci) * Lseq + l0 + l);
    }
    for (int e = tid; e < 4096; e += 256) {
        int o = e >> 6, ci = e & 63;
        sw[ci * 68 + o] = W[(size_t)(ob0 + o) * 64 + ci];
    }
    __syncthreads();
#pragma unroll 4
    for (int ci = 0; ci < 64; ci++) {
        float4 wv = *(const float4*)(sw + ci * 68 + ty * 4);
        float4 xv = *(const float4*)(sx + ci * 68 + tx * 4);
        float wr[4] = {wv.x, wv.y, wv.z, wv.w};
        float xr[4] = {xv.x, xv.y, xv.z, xv.w};
#pragma unroll
        for (int i = 0; i < 4; i++)
#pragma unroll
            for (int j = 0; j < 4; j++) acc[i][j] += wr[i] * xr[j];
    }
    int lx = tx * 4;
#pragma unroll
    for (int i = 0; i < 4; i++) {
        int o = ob0 + ty * 4 + i;
        float bo = bias[o];
        float4 ov;
        ov.x = fmaxf(acc[i][0] + bo, 0.f);
        ov.y = fmaxf(acc[i][1] + bo, 0.f);
        ov.z = fmaxf(acc[i][2] + bo, 0.f);
        ov.w = fmaxf(acc[i][3] + bo, 0.f);
        *(float4*)(out + ((size_t)b * 256 + o) * Lseq + l0 + lx) = ov;
    }
}

// ---------------- launch ----------------
extern "C" void kernel_launch(void* const* d_in, const int* in_sizes, int n_in,
                              void* d_out, int out_size)
{
    const float* q       = (const float*)d_in[0];
    const float* wq_pw   = (const float*)d_in[1];
    const float* wq_gate = (const float*)d_in[2];
    const float* wq_dw3  = (const float*)d_in[3];
    const float* wq_dw15 = (const float*)d_in[4];
    const float* wk_pw   = (const float*)d_in[5];
    const float* wk_gate = (const float*)d_in[6];
    const float* wk_dw3  = (const float*)d_in[7];
    const float* wk_dw15 = (const float*)d_in[8];
    const float* wv_pw   = (const float*)d_in[9];
    const float* wv_gate = (const float*)d_in[10];
    const float* wv_dw3  = (const float*)d_in[11];
    const float* wv_dw15 = (const float*)d_in[12];
    const float* w_unify = (const float*)d_in[13];
    const float* b_unify = (const float*)d_in[14];
    const float* ln1_g   = (const float*)d_in[15];
    const float* ln1_b   = (const float*)d_in[16];
    const float* ln2_g   = (const float*)d_in[17];
    const float* ln2_b   = (const float*)d_in[18];
    const float* ffn_w1  = (const float*)d_in[19];
    const float* ffn_b1  = (const float*)d_in[20];
    const float* ffn_w2  = (const float*)d_in[21];
    const float* ffn_b2  = (const float*)d_in[22];
    float* out = (float*)d_out;

    void *pPW, *pWF, *pQ, *pK, *pV, *pATT, *pY, *pH;
    cudaGetSymbolAddress(&pPW, g_PW);
    cudaGetSymbolAddress(&pWF, g_WF);
    cudaGetSymbolAddress(&pQ, g_Q);
    cudaGetSymbolAddress(&pK, g_K);
    cudaGetSymbolAddress(&pV, g_V);
    cudaGetSymbolAddress(&pATT, g_ATT);
    cudaGetSymbolAddress(&pY, g_Y);
    cudaGetSymbolAddress(&pH, g_H);

    cudaFuncSetAttribute(qkv_kernel, cudaFuncAttributeMaxDynamicSharedMemorySize, 65536);

    combine_kernel<<<6, 256>>>(
        wq_pw, wq_gate, wq_dw3, wq_dw15,
        wk_pw, wk_gate, wk_dw3, wk_dw15,
        wv_pw, wv_gate, wv_dw3, wv_dw15,
        (float*)pPW, (float*)pWF);

    qkv_kernel<<<dim3(8, 48, 16), 256, 65536>>>(
        q, (const float*)pPW, (const float*)pWF,
        (float*)pQ, (float*)pK, (float*)pV);

    attn_bf16<<<dim3(8, 128), 256>>>(
        (const float*)pQ, (const float*)pK, (const float*)pV, (float*)pATT);

    gemm_res_ln_kernel<<<dim3(16, 16), 256>>>(
        (const float*)pATT, w_unify, b_unify, q, ln1_g, ln1_b, (float*)pY, 512);

    ffn1_kernel<<<dim3(16, 4, 16), 256>>>(
        (const float*)pY, ffn_w1, ffn_b1, (float*)pH);

    gemm_res_ln_kernel<<<dim3(16, 16), 256>>>(
        (const float*)pH, ffn_w2, ffn_b2, (const float*)pY, ln2_g, ln2_b, out, 256);
}

// round 9
// speedup vs baseline: 1.1183x; 1.1183x over previous
#include <cuda_runtime.h>
#include <cuda_bf16.h>
#include <math.h>
#include <stdint.h>

#define Bsz  16
#define Cdim 64
#define Lseq 1024
#define Hn   8
#define HC   512
#define NH   128   // B*H batch-heads

// ---------------- scratch (static device memory; no allocations) ----------------
__device__ float g_PW[1536 * 64];             // packed pointwise weights (q|k|v)
__device__ float g_WF[1536 * 15];             // combined 15-tap depthwise weights
__device__ __nv_bfloat16 g_Q[NH * Lseq * Cdim];  // (n, l, c) bf16, pre-scaled x0.125
__device__ __nv_bfloat16 g_K[NH * Lseq * Cdim];  // (n, l, c) bf16
__device__ __nv_bfloat16 g_V[NH * Cdim * Lseq];  // (n, c, l) bf16
__device__ float g_ATT[Bsz * HC * Lseq];      // (b, hc, l)
__device__ float g_Y[Bsz * Cdim * Lseq];      // after LN1
__device__ float g_H[Bsz * 4 * Cdim * Lseq];  // FFN hidden

__device__ __forceinline__ uint32_t bfpack(float lo, float hi) {
    __nv_bfloat162 h = __floats2bfloat162_rn(lo, hi);
    return *reinterpret_cast<uint32_t*>(&h);
}
__device__ __forceinline__ uint32_t smem_u32(const void* p) {
    uint32_t a;
    asm("{ .reg .u64 t; cvta.to.shared.u64 t, %1; cvt.u32.u64 %0, t; }" : "=r"(a) : "l"(p));
    return a;
}

// D += A(16x16 bf16 row) * B(16x8 bf16 col)
__device__ __forceinline__ void mma_bf16(float* c, const uint32_t* a, uint32_t b0, uint32_t b1) {
    asm volatile(
        "mma.sync.aligned.m16n8k16.row.col.f32.bf16.bf16.f32 "
        "{%0,%1,%2,%3}, {%4,%5,%6,%7}, {%8,%9}, {%0,%1,%2,%3};"
        : "+f"(c[0]), "+f"(c[1]), "+f"(c[2]), "+f"(c[3])
        : "r"(a[0]), "r"(a[1]), "r"(a[2]), "r"(a[3]), "r"(b0), "r"(b1));
}
__device__ __forceinline__ void ldsm4(uint32_t& r0, uint32_t& r1, uint32_t& r2, uint32_t& r3,
                                      uint32_t addr) {
    asm volatile("ldmatrix.sync.aligned.m8n8.x4.shared.b16 {%0,%1,%2,%3}, [%4];"
                 : "=r"(r0), "=r"(r1), "=r"(r2), "=r"(r3) : "r"(addr));
}
#define CP16(dst, src) \
    asm volatile("cp.async.cg.shared.global [%0], [%1], 16;" :: "r"(dst), "l"(src))
#define CP_COMMIT() asm volatile("cp.async.commit_group;" ::: "memory")
#define CP_WAIT1()  asm volatile("cp.async.wait_group 1;" ::: "memory")

// ---------------- K0: fold gate softmax into combined conv weights ----------------
__global__ void combine_kernel(
    const float* __restrict__ pw0, const float* __restrict__ gt0,
    const float* __restrict__ d3_0, const float* __restrict__ d15_0,
    const float* __restrict__ pw1, const float* __restrict__ gt1,
    const float* __restrict__ d3_1, const float* __restrict__ d15_1,
    const float* __restrict__ pw2, const float* __restrict__ gt2,
    const float* __restrict__ d3_2, const float* __restrict__ d15_2,
    float* __restrict__ PW, float* __restrict__ WF)
{
    int o = blockIdx.x * 256 + threadIdx.x;
    if (o >= 1536) return;
    int s = o >> 9, lc = o & 511;
    const float *pw, *gt, *d3, *d15;
    if (s == 0)      { pw = pw0; gt = gt0; d3 = d3_0; d15 = d15_0; }
    else if (s == 1) { pw = pw1; gt = gt1; d3 = d3_1; d15 = d15_1; }
    else             { pw = pw2; gt = gt2; d3 = d3_2; d15 = d15_2; }
    float a = gt[0], b = gt[1];
    float mx = fmaxf(a, b);
    float e0 = expf(a - mx), e1 = expf(b - mx);
    float inv = 1.0f / (e0 + e1);
    float ga = e0 * inv, gb = e1 * inv;
    for (int c = 0; c < 64; c++) PW[(size_t)o * 64 + c] = pw[(size_t)lc * 64 + c];
    for (int t = 0; t < 15; t++) {
        float w = gb * d15[lc * 15 + t];
        if (t >= 6 && t < 9) w += ga * d3[lc * 3 + (t - 6)];
        WF[o * 15 + t] = w;
    }
}

// ---------------- K1: fused pointwise GEMM + depthwise conv15 -> Q/K/V (bf16 out) ----------------
__global__ __launch_bounds__(256) void qkv_kernel(
    const float* __restrict__ q,
    const float* __restrict__ PW, const float* __restrict__ WF,
    __nv_bfloat16* __restrict__ Qp, __nv_bfloat16* __restrict__ Kp,
    __nv_bfloat16* __restrict__ Vp)
{
    extern __shared__ float sm1[];
    float* xs  = sm1;               // [64][144]
    float* mid = xs + 64 * 144;     // [32][144]
    float* spw = mid + 32 * 144;    // [32][64]
    float* swf = spw + 32 * 64;     // [32][16]
    int tid = threadIdx.x;
    int l0 = blockIdx.x * 128;
    int o0 = blockIdx.y * 32;
    int b  = blockIdx.z;

    for (int e = tid; e < 64 * 144; e += 256) {
        int c = e / 144, j = e - c * 144;
        int gl = l0 - 7 + j;
        float v = 0.f;
        if (gl >= 0 && gl < Lseq) v = q[((size_t)b * 64 + c) * Lseq + gl];
        xs[c * 144 + j] = v;
    }
    for (int e = tid; e < 32 * 64; e += 256) spw[e] = PW[(size_t)o0 * 64 + e];
    for (int e = tid; e < 32 * 15; e += 256) {
        int o = e / 15, t = e - o * 15;
        swf[o * 16 + t] = WF[(size_t)(o0 + o) * 15 + t];
    }
    __syncthreads();

    for (int e = tid; e < 32 * 36; e += 256) {
        int o = e / 36, jq = e - o * 36;
        const float* pwrow = spw + o * 64;
        const float* xcol  = xs + jq * 4;
        float4 acc = make_float4(0.f, 0.f, 0.f, 0.f);
#pragma unroll 8
        for (int c = 0; c < 64; c++) {
            float w = pwrow[c];
            float4 xv = *(const float4*)(xcol + c * 144);
            acc.x += w * xv.x; acc.y += w * xv.y; acc.z += w * xv.z; acc.w += w * xv.w;
        }
        *(float4*)(mid + o * 144 + jq * 4) = acc;
    }
    __syncthreads();

    int s = o0 >> 9;
    float scale = (s == 0) ? 0.125f : 1.0f;
    for (int e = tid; e < 32 * 128; e += 256) {
        int o = e >> 7, i = e & 127;
        const float* mrow = mid + o * 144;
        const float* wrow = swf + o * 16;
        float acc = 0.f;
#pragma unroll
        for (int t = 0; t < 15; t++) acc += wrow[t] * mrow[i + t];
        acc *= scale;
        int og = o0 + o;
        int ch = og & 511;
        int head = ch >> 6, c = ch & 63;
        size_t n = (size_t)b * 8 + head;
        __nv_bfloat16 hv = __float2bfloat16_rn(acc);
        if (s == 2) {
            Vp[(n * 64 + c) * Lseq + l0 + i] = hv;                  // (n, c, l)
        } else {
            __nv_bfloat16* base = (s == 0) ? Qp : Kp;
            base[(n * Lseq + l0 + i) * 64 + c] = hv;                // (n, l, c)
        }
    }
}

// ---------------- K2: flash attention: bf16 mma + ldmatrix + cp.async double buffer ----------------
// grid (8, 128); 256 threads (8 warps x 16 q-rows). static smem 36864 B.
#define KVS 72              // padded row stride (bf16 elems); 144 B
#define BUFE (64 * KVS)     // elems per buffer
__global__ __launch_bounds__(256, 2) void attn_bf16(
    const __nv_bfloat16* __restrict__ Qt, const __nv_bfloat16* __restrict__ Kt,
    const __nv_bfloat16* __restrict__ Vg, float* __restrict__ att)
{
    __shared__ __nv_bfloat16 Ks[2][BUFE];
    __shared__ __nv_bfloat16 Vs[2][BUFE];
    int tid = threadIdx.x, w = tid >> 5, lane = tid & 31;
    int g = lane >> 2, r = lane & 3;
    int n = blockIdx.y, q0 = blockIdx.x * 128;

    const __nv_bfloat16* Qb = Qt + (size_t)n * (Lseq * 64) + (size_t)(q0 + w * 16) * 64;
    const __nv_bfloat16* Kb = Kt + (size_t)n * (Lseq * 64);
    const __nv_bfloat16* Vb = Vg + (size_t)n * (64 * Lseq);

    // cp.async granule assignment (4 x 16B per thread per tile)
    int eK0 = tid, eK1 = tid + 256;          // K granules (0..511)
    int eV0 = tid, eV1 = tid + 256;          // V granules (0..511)
    int kr0 = eK0 >> 3, kg0 = eK0 & 7;
    int kr1 = eK1 >> 3, kg1 = eK1 & 7;
    uint32_t ks_base = smem_u32(&Ks[0][0]);
    uint32_t vs_base = smem_u32(&Vs[0][0]);
    uint32_t kd0 = ks_base + (kr0 * KVS + kg0 * 8) * 2;
    uint32_t kd1 = ks_base + (kr1 * KVS + kg1 * 8) * 2;
    uint32_t vd0 = vs_base + (kr0 * KVS + kg0 * 8) * 2;
    uint32_t vd1 = vs_base + (kr1 * KVS + kg1 * 8) * 2;

    // ldmatrix per-lane base: sel = lane>>3 picks (keyblk, c-half)
    int sel = lane >> 3, lrow = lane & 7;
    int mrow = ((sel >> 1) << 3) + lrow;      // row within 16-row pair block
    int mcol = (sel & 1) << 3;                // c offset 0 / 8
    uint32_t kls = ks_base + (mrow * KVS + mcol) * 2;
    uint32_t vls = vs_base + (mrow * KVS + mcol) * 2;

    // ---- Q A-fragments direct from gmem (bf16, pre-scaled) ----
    uint32_t qf[16];
#pragma unroll
    for (int kc = 0; kc < 4; kc++) {
        qf[kc * 4 + 0] = *(const uint32_t*)(Qb + (size_t)g * 64 + kc * 16 + 2 * r);
        qf[kc * 4 + 1] = *(const uint32_t*)(Qb + (size_t)(g + 8) * 64 + kc * 16 + 2 * r);
        qf[kc * 4 + 2] = *(const uint32_t*)(Qb + (size_t)g * 64 + kc * 16 + 2 * r + 8);
        qf[kc * 4 + 3] = *(const uint32_t*)(Qb + (size_t)(g + 8) * 64 + kc * 16 + 2 * r + 8);
    }

    // ---- prologue: stage tiles 0 and 1 ----
#pragma unroll
    for (int t = 0; t < 2; t++) {
        int k0 = t * 64;
        uint32_t bo = t * BUFE * 2;
        CP16(kd0 + bo, Kb + (size_t)(k0 + kr0) * 64 + kg0 * 8);
        CP16(kd1 + bo, Kb + (size_t)(k0 + kr1) * 64 + kg1 * 8);
        CP16(vd0 + bo, Vb + (size_t)kr0 * Lseq + k0 + kg0 * 8);
        CP16(vd1 + bo, Vb + (size_t)kr1 * Lseq + k0 + kg1 * 8);
        CP_COMMIT();
    }

    float oacc[32];
#pragma unroll
    for (int i = 0; i < 32; i++) oacc[i] = 0.f;
    float m0 = -INFINITY, m1 = -INFINITY, l0 = 0.f, l1 = 0.f;

    for (int kt = 0; kt < 16; kt++) {
        CP_WAIT1();
        __syncthreads();
        uint32_t bo = (kt & 1) * BUFE * 2;

        // ---- S = Q K^T : ldmatrix.x4 -> 2 mmas each ----
        float sacc[32];
#pragma unroll
        for (int i = 0; i < 32; i++) sacc[i] = 0.f;
#pragma unroll
        for (int kc = 0; kc < 4; kc++) {
#pragma unroll
            for (int nb2 = 0; nb2 < 4; nb2++) {
                uint32_t b0, b1, b2, b3;
                ldsm4(b0, b1, b2, b3, kls + bo + nb2 * (16 * KVS * 2) + kc * 32);
                mma_bf16(sacc + (2 * nb2) * 4,     qf + kc * 4, b0, b1);
                mma_bf16(sacc + (2 * nb2 + 1) * 4, qf + kc * 4, b2, b3);
            }
        }

        // ---- online softmax (quad-local rows g / g+8) ----
        float tm0 = -INFINITY, tm1 = -INFINITY;
#pragma unroll
        for (int nb = 0; nb < 8; nb++) {
            tm0 = fmaxf(tm0, fmaxf(sacc[nb * 4 + 0], sacc[nb * 4 + 1]));
            tm1 = fmaxf(tm1, fmaxf(sacc[nb * 4 + 2], sacc[nb * 4 + 3]));
        }
        tm0 = fmaxf(tm0, __shfl_xor_sync(0xffffffffu, tm0, 1));
        tm0 = fmaxf(tm0, __shfl_xor_sync(0xffffffffu, tm0, 2));
        tm1 = fmaxf(tm1, __shfl_xor_sync(0xffffffffu, tm1, 1));
        tm1 = fmaxf(tm1, __shfl_xor_sync(0xffffffffu, tm1, 2));
        float mn0 = fmaxf(m0, tm0), mn1 = fmaxf(m1, tm1);
        float al0 = __expf(m0 - mn0), al1 = __expf(m1 - mn1);
        m0 = mn0; m1 = mn1;
        float s0 = 0.f, s1 = 0.f;
        uint32_t plo[8], phi[8];
#pragma unroll
        for (int nb = 0; nb < 8; nb++) {
            float p0 = __expf(sacc[nb * 4 + 0] - mn0);
            float p1 = __expf(sacc[nb * 4 + 1] - mn0);
            float p2 = __expf(sacc[nb * 4 + 2] - mn1);
            float p3 = __expf(sacc[nb * 4 + 3] - mn1);
            s0 += p0 + p1; s1 += p2 + p3;
            plo[nb] = bfpack(p0, p1);
            phi[nb] = bfpack(p2, p3);
        }
        s0 += __shfl_xor_sync(0xffffffffu, s0, 1);
        s0 += __shfl_xor_sync(0xffffffffu, s0, 2);
        s1 += __shfl_xor_sync(0xffffffffu, s1, 1);
        s1 += __shfl_xor_sync(0xffffffffu, s1, 2);
        l0 = l0 * al0 + s0;
        l1 = l1 * al1 + s1;
#pragma unroll
        for (int nb = 0; nb < 8; nb++) {
            oacc[nb * 4 + 0] *= al0; oacc[nb * 4 + 1] *= al0;
            oacc[nb * 4 + 2] *= al1; oacc[nb * 4 + 3] *= al1;
        }

        // ---- O += P V^T ----
#pragma unroll
        for (int kc = 0; kc < 4; kc++) {
            uint32_t pa[4] = {plo[2 * kc], phi[2 * kc], plo[2 * kc + 1], phi[2 * kc + 1]};
#pragma unroll
            for (int nb2 = 0; nb2 < 4; nb2++) {
                uint32_t b0, b1, b2, b3;
                ldsm4(b0, b1, b2, b3, vls + bo + nb2 * (16 * KVS * 2) + kc * 32);
                mma_bf16(oacc + (2 * nb2) * 4,     pa, b0, b1);
                mma_bf16(oacc + (2 * nb2 + 1) * 4, pa, b2, b3);
            }
        }

        __syncthreads();   // all warps done with buf (kt&1) before refill
        if (kt < 14) {
            int k0 = (kt + 2) * 64;
            uint32_t nb_ = (kt & 1) * BUFE * 2;
            CP16(kd0 + nb_, Kb + (size_t)(k0 + kr0) * 64 + kg0 * 8);
            CP16(kd1 + nb_, Kb + (size_t)(k0 + kr1) * 64 + kg1 * 8);
            CP16(vd0 + nb_, Vb + (size_t)kr0 * Lseq + k0 + kg0 * 8);
            CP16(vd1 + nb_, Vb + (size_t)kr1 * Lseq + k0 + kg1 * 8);
        }
        CP_COMMIT();       // empty group when kt>=14 keeps wait-count invariant
    }

    // ---- epilogue: O / l -> att (b, head*64+c, q) ----
    float inv0 = 1.0f / l0, inv1 = 1.0f / l1;
    int bb = n >> 3, head = n & 7;
    int qg0 = q0 + w * 16 + g, qg1 = qg0 + 8;
    float* ab = att + ((size_t)bb * 512 + head * 64) * Lseq;
#pragma unroll
    for (int nb = 0; nb < 8; nb++) {
        int c = nb * 8 + 2 * r;
        ab[(size_t)c * Lseq + qg0]       = oacc[nb * 4 + 0] * inv0;
        ab[(size_t)(c + 1) * Lseq + qg0] = oacc[nb * 4 + 1] * inv0;
        ab[(size_t)c * Lseq + qg1]       = oacc[nb * 4 + 2] * inv1;
        ab[(size_t)(c + 1) * Lseq + qg1] = oacc[nb * 4 + 3] * inv1;
    }
}

// ---------------- K3/K5: (64 x INC) GEMM + bias + residual + channel LayerNorm ----------------
__global__ __launch_bounds__(256) void gemm_res_ln_kernel(
    const float* __restrict__ X, const float* __restrict__ W,
    const float* __restrict__ bias, const float* __restrict__ res,
    const float* __restrict__ gam, const float* __restrict__ bet,
    float* __restrict__ out, int INC)
{
    __shared__ float sx[64 * 68];
    __shared__ float sw[64 * 68];
    int tid = threadIdx.x;
    int l0 = blockIdx.x * 64;
    int b  = blockIdx.y;
    int ty = tid >> 4, tx = tid & 15;
    float acc[4][4];
#pragma unroll
    for (int i = 0; i < 4; i++)
#pragma unroll
        for (int j = 0; j < 4; j++) acc[i][j] = 0.f;

    for (int cb = 0; cb < INC; cb += 64) {
        __syncthreads();
        for (int e = tid * 4; e < 4096; e += 1024) {
            int ci = e >> 6, l = e & 63;
            *(float4*)(sx + ci * 68 + l) =
                *(const float4*)(X + ((size_t)b * INC + cb + ci) * Lseq + l0 + l);
        }
        for (int e = tid; e < 4096; e += 256) {
            int o = e >> 6, ci = e & 63;
            sw[ci * 68 + o] = W[(size_t)o * INC + cb + ci];
        }
        __syncthreads();
#pragma unroll 4
        for (int ci = 0; ci < 64; ci++) {
            float4 wv = *(const float4*)(sw + ci * 68 + ty * 4);
            float4 xv = *(const float4*)(sx + ci * 68 + tx * 4);
            float wr[4] = {wv.x, wv.y, wv.z, wv.w};
            float xr[4] = {xv.x, xv.y, xv.z, xv.w};
#pragma unroll
            for (int i = 0; i < 4; i++)
#pragma unroll
                for (int j = 0; j < 4; j++) acc[i][j] += wr[i] * xr[j];
        }
    }
    int ob = ty * 4, lx = tx * 4;
    float vals[4][4];
#pragma unroll
    for (int i = 0; i < 4; i++) {
        int o = ob + i;
        float bo = bias[o];
        float4 rv = *(const float4*)(res + ((size_t)b * 64 + o) * Lseq + l0 + lx);
        vals[i][0] = acc[i][0] + bo + rv.x;
        vals[i][1] = acc[i][1] + bo + rv.y;
        vals[i][2] = acc[i][2] + bo + rv.z;
        vals[i][3] = acc[i][3] + bo + rv.w;
    }
    __syncthreads();
    float* red1 = sw;
    float* red2 = sw + 1024;
    float* mu_s = sw + 2048;
    float* iv_s = sw + 2112;
#pragma unroll
    for (int j = 0; j < 4; j++) {
        float s1 = vals[0][j] + vals[1][j] + vals[2][j] + vals[3][j];
        float s2 = vals[0][j] * vals[0][j] + vals[1][j] * vals[1][j] +
                   vals[2][j] * vals[2][j] + vals[3][j] * vals[3][j];
        red1[ty * 64 + lx + j] = s1;
        red2[ty * 64 + lx + j] = s2;
    }
    __syncthreads();
    if (tid < 64) {
        float s1 = 0.f, s2 = 0.f;
#pragma unroll
        for (int r = 0; r < 16; r++) { s1 += red1[r * 64 + tid]; s2 += red2[r * 64 + tid]; }
        float mu = s1 * (1.0f / 64.0f);
        float var = s2 * (1.0f / 64.0f) - mu * mu;
        mu_s[tid] = mu;
        iv_s[tid] = rsqrtf(var + 1e-5f);
    }
    __syncthreads();
#pragma unroll
    for (int i = 0; i < 4; i++) {
        int o = ob + i;
        float gg = gam[o], bb = bet[o];
        float4 ov;
        ov.x = (vals[i][0] - mu_s[lx + 0]) * iv_s[lx + 0] * gg + bb;
        ov.y = (vals[i][1] - mu_s[lx + 1]) * iv_s[lx + 1] * gg + bb;
        ov.z = (vals[i][2] - mu_s[lx + 2]) * iv_s[lx + 2] * gg + bb;
        ov.w = (vals[i][3] - mu_s[lx + 3]) * iv_s[lx + 3] * gg + bb;
        *(float4*)(out + ((size_t)b * 64 + o) * Lseq + l0 + lx) = ov;
    }
}

// ---------------- K4: FFN up-projection (256x64) + bias + ReLU ----------------
__global__ __launch_bounds__(256) void ffn1_kernel(
    const float* __restrict__ X, const float* __restrict__ W,
    const float* __restrict__ bias, float* __restrict__ out)
{
    __shared__ float sx[64 * 68];
    __shared__ float sw[64 * 68];
    int tid = threadIdx.x;
    int l0  = blockIdx.x * 64;
    int ob0 = blockIdx.y * 64;
    int b   = blockIdx.z;
    int ty = tid >> 4, tx = tid & 15;
    float acc[4][4];
#pragma unroll
    for (int i = 0; i < 4; i++)
#pragma unroll
        for (int j = 0; j < 4; j++) acc[i][j] = 0.f;

    for (int e = tid * 4; e < 4096; e += 1024) {
        int ci = e >> 6, l = e & 63;
        *(float4*)(sx + ci * 68 + l) =
            *(const float4*)(X + ((size_t)b * 64 + ci) * Lseq + l0 + l);
    }
    for (int e = tid; e < 4096; e += 256) {
        int o = e >> 6, ci = e & 63;
        sw[ci * 68 + o] = W[(size_t)(ob0 + o) * 64 + ci];
    }
    __syncthreads();
#pragma unroll 4
    for (int ci = 0; ci < 64; ci++) {
        float4 wv = *(const float4*)(sw + ci * 68 + ty * 4);
        float4 xv = *(const float4*)(sx + ci * 68 + tx * 4);
        float wr[4] = {wv.x, wv.y, wv.z, wv.w};
        float xr[4] = {xv.x, xv.y, xv.z, xv.w};
#pragma unroll
        for (int i = 0; i < 4; i++)
#pragma unroll
            for (int j = 0; j < 4; j++) acc[i][j] += wr[i] * xr[j];
    }
    int lx = tx * 4;
#pragma unroll
    for (int i = 0; i < 4; i++) {
        int o = ob0 + ty * 4 + i;
        float bo = bias[o];
        float4 ov;
        ov.x = fmaxf(acc[i][0] + bo, 0.f);
        ov.y = fmaxf(acc[i][1] + bo, 0.f);
        ov.z = fmaxf(acc[i][2] + bo, 0.f);
        ov.w = fmaxf(acc[i][3] + bo, 0.f);
        *(float4*)(out + ((size_t)b * 256 + o) * Lseq + l0 + lx) = ov;
    }
}

// ---------------- launch ----------------
extern "C" void kernel_launch(void* const* d_in, const int* in_sizes, int n_in,
                              void* d_out, int out_size)
{
    const float* q       = (const float*)d_in[0];
    const float* wq_pw   = (const float*)d_in[1];
    const float* wq_gate = (const float*)d_in[2];
    const float* wq_dw3  = (const float*)d_in[3];
    const float* wq_dw15 = (const float*)d_in[4];
    const float* wk_pw   = (const float*)d_in[5];
    const float* wk_gate = (const float*)d_in[6];
    const float* wk_dw3  = (const float*)d_in[7];
    const float* wk_dw15 = (const float*)d_in[8];
    const float* wv_pw   = (const float*)d_in[9];
    const float* wv_gate = (const float*)d_in[10];
    const float* wv_dw3  = (const float*)d_in[11];
    const float* wv_dw15 = (const float*)d_in[12];
    const float* w_unify = (const float*)d_in[13];
    const float* b_unify = (const float*)d_in[14];
    const float* ln1_g   = (const float*)d_in[15];
    const float* ln1_b   = (const float*)d_in[16];
    const float* ln2_g   = (const float*)d_in[17];
    const float* ln2_b   = (const float*)d_in[18];
    const float* ffn_w1  = (const float*)d_in[19];
    const float* ffn_b1  = (const float*)d_in[20];
    const float* ffn_w2  = (const float*)d_in[21];
    const float* ffn_b2  = (const float*)d_in[22];
    float* out = (float*)d_out;

    void *pPW, *pWF, *pQ, *pK, *pV, *pATT, *pY, *pH;
    cudaGetSymbolAddress(&pPW, g_PW);
    cudaGetSymbolAddress(&pWF, g_WF);
    cudaGetSymbolAddress(&pQ, g_Q);
    cudaGetSymbolAddress(&pK, g_K);
    cudaGetSymbolAddress(&pV, g_V);
    cudaGetSymbolAddress(&pATT, g_ATT);
    cudaGetSymbolAddress(&pY, g_Y);
    cudaGetSymbolAddress(&pH, g_H);

    cudaFuncSetAttribute(qkv_kernel, cudaFuncAttributeMaxDynamicSharedMemorySize, 65536);

    combine_kernel<<<6, 256>>>(
        wq_pw, wq_gate, wq_dw3, wq_dw15,
        wk_pw, wk_gate, wk_dw3, wk_dw15,
        wv_pw, wv_gate, wv_dw3, wv_dw15,
        (float*)pPW, (float*)pWF);

    qkv_kernel<<<dim3(8, 48, 16), 256, 65536>>>(
        q, (const float*)pPW, (const float*)pWF,
        (__nv_bfloat16*)pQ, (__nv_bfloat16*)pK, (__nv_bfloat16*)pV);

    attn_bf16<<<dim3(8, 128), 256>>>(
        (const __nv_bfloat16*)pQ, (const __nv_bfloat16*)pK,
        (const __nv_bfloat16*)pV, (float*)pATT);

    gemm_res_ln_kernel<<<dim3(16, 16), 256>>>(
        (const float*)pATT, w_unify, b_unify, q, ln1_g, ln1_b, (float*)pY, 512);

    ffn1_kernel<<<dim3(16, 4, 16), 256>>>(
        (const float*)pY, ffn_w1, ffn_b1, (float*)pH);

    gemm_res_ln_kernel<<<dim3(16, 16), 256>>>(
        (const float*)pH, ffn_w2, ffn_b2, (const float*)pY, ln2_g, ln2_b, out, 256);
}